// round 13
// baseline (speedup 1.0000x reference)
#include <cuda_runtime.h>
#include <cstdint>

#define BB 16
#define TT 32
#define FF 8
#define SS 256
#define HH 512
#define KX 520         // F + H
#define GRID 148
#define NTH 512
#define NLEAF 8

// ---------------- device scratch (static, no allocation) ----------------
__device__ float g_encW2[BB * SS * HH];   // 8 MB, enc @ W2^T (step-invariant)
__device__ float g_hW1[BB * HH];
__device__ float g_scores[BB * SS];       // holds exp(score)
__device__ float g_weighted[BB * HH];
__device__ float g_xin[BB * FF];
__device__ float g_h0[2][BB * HH];
__device__ float g_h1[2][BB * HH];
__device__ int   g_leaf[NLEAF * 256];     // padded leaf counters (1KB apart)
__device__ int   g_rootc[256];
__device__ int   g_gen;                   // monotonic across replays

// ---------------- helpers ----------------
__device__ __forceinline__ float2 ffma2(float2 a, float2 b, float2 c) {
    unsigned long long A = *reinterpret_cast<unsigned long long*>(&a);
    unsigned long long Bv = *reinterpret_cast<unsigned long long*>(&b);
    unsigned long long C = *reinterpret_cast<unsigned long long*>(&c);
    unsigned long long D;
    asm("fma.rn.f32x2 %0, %1, %2, %3;" : "=l"(D) : "l"(A), "l"(Bv), "l"(C));
    return *reinterpret_cast<float2*>(&D);
}
__device__ __forceinline__ float htanh(float x) {
    float y; asm("tanh.approx.f32 %0, %1;" : "=f"(y) : "f"(x)); return y;
}
__device__ __forceinline__ float hsig(float x) {
    return fmaf(htanh(0.5f * x), 0.5f, 0.5f);
}
__device__ __forceinline__ float  lcg(const float* p)  { return __ldcg(p); }
__device__ __forceinline__ float2 lcg2(const float* p) { return __ldcg(reinterpret_cast<const float2*>(p)); }

// Tree grid barrier. No gpu-scope fences (CCTL.IVALL would flush L1D);
// mutable cross-block data is always read via .cg (L2) instead.
__device__ __forceinline__ void gridbar() {
    __syncthreads();
    if (threadIdx.x == 0) {
        int bi = blockIdx.x;
        int leaf = bi & (NLEAF - 1);
        int leafsz = (leaf < 4) ? 19 : 18;   // 148 = 4*19 + 4*18
        int gen;
        asm volatile("ld.relaxed.gpu.s32 %0, [%1];" : "=r"(gen) : "l"(&g_gen) : "memory");
        int prev;
        asm volatile("atom.acq_rel.gpu.add.s32 %0, [%1], %2;"
                     : "=r"(prev) : "l"(&g_leaf[leaf * 256]), "r"(1) : "memory");
        if (prev == leafsz - 1) {
            asm volatile("st.relaxed.gpu.s32 [%0], %1;" :: "l"(&g_leaf[leaf * 256]), "r"(0) : "memory");
            int p2;
            asm volatile("atom.acq_rel.gpu.add.s32 %0, [%1], %2;"
                         : "=r"(p2) : "l"(&g_rootc[0]), "r"(1) : "memory");
            if (p2 == NLEAF - 1) {
                asm volatile("st.relaxed.gpu.s32 [%0], %1;" :: "l"(&g_rootc[0]), "r"(0) : "memory");
                asm volatile("st.release.gpu.s32 [%0], %1;" :: "l"(&g_gen), "r"(gen + 1) : "memory");
            }
        }
        int cur;
        do {
            asm volatile("ld.relaxed.gpu.s32 %0, [%1];" : "=r"(cur) : "l"(&g_gen) : "memory");
        } while (cur == gen);
        asm volatile("ld.acquire.gpu.s32 %0, [%1];" : "=r"(cur) : "l"(&g_gen) : "memory");
    }
    __syncthreads();
}

// ---------------- encW2 = enc @ W2^T  (prologue GEMM) ----------------
__global__ void __launch_bounds__(256) kEncW2(const float* __restrict__ enc,
                                              const float* __restrict__ attnW) {
    __shared__ float As[32][68];
    __shared__ float Bs[32][72];
    int Mblk = blockIdx.y * 64;
    int Nblk = blockIdx.x * 64;
    int tid = threadIdx.x;
    int tx = tid & 15, ty = tid >> 4;

    float2 acc[4][2];
#pragma unroll
    for (int i = 0; i < 4; i++) { acc[i][0] = make_float2(0.f, 0.f); acc[i][1] = make_float2(0.f, 0.f); }

    const float* Ag = enc + (size_t)Mblk * 512;
    const float* Bg = attnW + (size_t)Nblk * 1024 + 512;

    for (int k0 = 0; k0 < 512; k0 += 32) {
#pragma unroll
        for (int r = 0; r < 2; r++) {
            int i = r * 256 + tid;
            int m = i >> 3, g = i & 7;
            float4 v = *reinterpret_cast<const float4*>(Ag + m * 512 + k0 + g * 4);
            As[g * 4 + 0][m] = v.x; As[g * 4 + 1][m] = v.y;
            As[g * 4 + 2][m] = v.z; As[g * 4 + 3][m] = v.w;
            float4 u = *reinterpret_cast<const float4*>(Bg + m * 1024 + k0 + g * 4);
            Bs[g * 4 + 0][m] = u.x; Bs[g * 4 + 1][m] = u.y;
            Bs[g * 4 + 2][m] = u.z; Bs[g * 4 + 3][m] = u.w;
        }
        __syncthreads();
#pragma unroll
        for (int kk = 0; kk < 32; kk++) {
            float4 a4 = *reinterpret_cast<const float4*>(&As[kk][ty * 4]);
            float2 b0 = *reinterpret_cast<const float2*>(&Bs[kk][tx * 4]);
            float2 b1 = *reinterpret_cast<const float2*>(&Bs[kk][tx * 4 + 2]);
            float2 aa;
            aa.x = aa.y = a4.x; acc[0][0] = ffma2(aa, b0, acc[0][0]); acc[0][1] = ffma2(aa, b1, acc[0][1]);
            aa.x = aa.y = a4.y; acc[1][0] = ffma2(aa, b0, acc[1][0]); acc[1][1] = ffma2(aa, b1, acc[1][1]);
            aa.x = aa.y = a4.z; acc[2][0] = ffma2(aa, b0, acc[2][0]); acc[2][1] = ffma2(aa, b1, acc[2][1]);
            aa.x = aa.y = a4.w; acc[3][0] = ffma2(aa, b0, acc[3][0]); acc[3][1] = ffma2(aa, b1, acc[3][1]);
        }
        __syncthreads();
    }
#pragma unroll
    for (int i = 0; i < 4; i++) {
        float* row = g_encW2 + (size_t)(Mblk + ty * 4 + i) * 512 + Nblk + tx * 4;
        *reinterpret_cast<float2*>(row) = acc[i][0];
        *reinterpret_cast<float2*>(row + 2) = acc[i][1];
    }
}

// ================== persistent-kernel phases ==================

// scores: warp per (b,s); stores exp(score) (scores bounded ~|20| -> safe)
__device__ __forceinline__ void scores_phase(const float* __restrict__ v_w) {
    int tid = threadIdx.x, w = tid >> 5, l = tid & 31;
    for (int pr = blockIdx.x * 16 + w; pr < BB * SS; pr += GRID * 16) {
        int b = pr >> 8;
        const float* e = g_encW2 + (size_t)pr * HH;
        const float* hr = g_hW1 + b * HH;
        float acc = 0.f;
#pragma unroll
        for (int i = 0; i < 16; i++) {
            int k = l + 32 * i;
            acc += htanh(e[k] + lcg(hr + k)) * v_w[k];
        }
#pragma unroll
        for (int off = 16; off > 0; off >>= 1) acc += __shfl_xor_sync(0xffffffffu, acc, off);
        if (l == 0) g_scores[pr] = __expf(acc);
    }
}

// weighted sum: block = (b, 64-h chunk); scores are already exp'ed
__device__ __forceinline__ void weighted_phase(float* sm, const float* __restrict__ enc) {
    int bi = blockIdx.x;
    if (bi >= 128) return;
    int tid = threadIdx.x;
    int b = bi >> 3, hc = bi & 7;
    float* wsm  = sm;          // 256 raw exps
    float* red  = sm + 256;    // 512
    float* wred = sm + 768;    // 16

    float e = (tid < 256) ? lcg(&g_scores[b * SS + tid]) : 0.f;
    if (tid < 256) wsm[tid] = e;
    float s = e;
#pragma unroll
    for (int off = 16; off > 0; off >>= 1) s += __shfl_xor_sync(0xffffffffu, s, off);
    if ((tid & 31) == 0) wred[tid >> 5] = s;
    __syncthreads();
    float tot = 0.f;
#pragma unroll
    for (int i = 0; i < 16; i++) tot += wred[i];
    float inv = __fdividef(1.f, tot);

    int h = hc * 64 + (tid & 63), sg = tid >> 6;
    const float* ep = enc + (size_t)b * SS * HH + h;
    float acc = 0.f;
#pragma unroll 8
    for (int s2 = sg; s2 < SS; s2 += 8) acc += wsm[s2] * ep[(size_t)s2 * HH];
    red[tid] = acc;
    __syncthreads();
    if (tid < 64) {
        float v = 0.f;
#pragma unroll
        for (int g = 0; g < 8; g++) v += red[tid + 64 * g];
        g_weighted[b * HH + hc * 64 + tid] = v * inv;
    }
}

// GRU layer: 128 blocks x 4 j; 16 warps = {gi,gh} x {4 j} x {2 K-halves}
// Layer0 x layout in smem: [weighted(512), xin(8)]; weight cols: xin first.
template <int LAYER>
__device__ __forceinline__ void gru_phase(float* sm, int p,
                                          const float* __restrict__ Wih,
                                          const float* __restrict__ Whh,
                                          const float* __restrict__ bih,
                                          const float* __restrict__ bhh) {
    int bi = blockIdx.x;
    if (bi >= 128) return;
    int tid = threadIdx.x;
    constexpr int K = (LAYER == 0) ? KX : HH;
    float* xp = sm;                 // 16 x K packed batch-pairs
    float* hp = sm + 16 * K;        // 16 x 512
    float* ex = hp + 16 * 512;      // [role2][kh2][j4][gate3][b16]

    const float* hold = (LAYER == 0) ? g_h0[p] : g_h1[p];
    float* hnew       = (LAYER == 0) ? g_h0[1 - p] : g_h1[1 - p];

    if (LAYER == 0) {
        for (int i = tid; i < 16 * 512; i += NTH) {
            int b = i >> 9, k = i & 511;
            xp[(b >> 1) * (2 * K) + 2 * k + (b & 1)] = lcg(g_weighted + b * HH + k);
        }
        if (tid < 128) {
            int b = tid >> 3, f = tid & 7;
            xp[(b >> 1) * (2 * K) + 2 * (512 + f) + (b & 1)] = lcg(g_xin + b * FF + f);
        }
    } else {
        const float* src0 = g_h0[1 - p];
        for (int i = tid; i < 16 * 512; i += NTH) {
            int b = i >> 9, k = i & 511;
            xp[(b >> 1) * 1024 + 2 * k + (b & 1)] = lcg(src0 + b * HH + k);
        }
    }
    for (int i = tid; i < 16 * 512; i += NTH) {
        int b = i >> 9, k = i & 511;
        hp[(b >> 1) * 1024 + 2 * k + (b & 1)] = lcg(hold + b * HH + k);
    }
    __syncthreads();

    int w = tid >> 5, l = tid & 31;
    int jrel = w & 3;
    int role = (w >> 2) & 1;       // 0 = gi, 1 = gh
    int kh = w >> 3;
    int j = bi * 4 + jrel;

    float2 a0[8], a1[8], a2[8];
#pragma unroll
    for (int bp = 0; bp < 8; bp++) { a0[bp] = make_float2(0.f, 0.f); a1[bp] = a0[bp]; a2[bp] = a0[bp]; }

    int k0 = l + kh * 32;
    if (role == 0) {
        const float2* src = reinterpret_cast<const float2*>(xp);
        const float* wr = Wih + (size_t)j * K + ((LAYER == 0) ? FF : 0);
        const float* wz = wr + (size_t)512 * K;
        const float* wn = wz + (size_t)512 * K;
#pragma unroll
        for (int ii = 0; ii < 8; ii++) {
            int k = k0 + ii * 64;
            float r_ = wr[k], z_ = wz[k], n_ = wn[k];
            float2 rr = make_float2(r_, r_), zz = make_float2(z_, z_), nn = make_float2(n_, n_);
#pragma unroll
            for (int bp = 0; bp < 8; bp++) {
                float2 x2 = src[bp * K + k];
                a0[bp] = ffma2(x2, rr, a0[bp]);
                a1[bp] = ffma2(x2, zz, a1[bp]);
                a2[bp] = ffma2(x2, nn, a2[bp]);
            }
        }
        if (LAYER == 0 && kh == 0 && l < FF) {
            // xin tail: weight cols 0..7, xp positions 512..519
            const float* wrb = Wih + (size_t)j * K;
            const float* wzb = wrb + (size_t)512 * K;
            const float* wnb = wzb + (size_t)512 * K;
            float r_ = wrb[l], z_ = wzb[l], n_ = wnb[l];
            float2 rr = make_float2(r_, r_), zz = make_float2(z_, z_), nn = make_float2(n_, n_);
            int k = 512 + l;
#pragma unroll
            for (int bp = 0; bp < 8; bp++) {
                float2 x2 = src[bp * K + k];
                a0[bp] = ffma2(x2, rr, a0[bp]);
                a1[bp] = ffma2(x2, zz, a1[bp]);
                a2[bp] = ffma2(x2, nn, a2[bp]);
            }
        }
    } else {
        const float2* src = reinterpret_cast<const float2*>(hp);
        const float* wr = Whh + (size_t)j * HH;
        const float* wz = wr + (size_t)512 * HH;
        const float* wn = wz + (size_t)512 * HH;
#pragma unroll
        for (int ii = 0; ii < 8; ii++) {
            int k = k0 + ii * 64;
            float r_ = wr[k], z_ = wz[k], n_ = wn[k];
            float2 rr = make_float2(r_, r_), zz = make_float2(z_, z_), nn = make_float2(n_, n_);
#pragma unroll
            for (int bp = 0; bp < 8; bp++) {
                float2 x2 = src[bp * 512 + k];
                a0[bp] = ffma2(x2, rr, a0[bp]);
                a1[bp] = ffma2(x2, zz, a1[bp]);
                a2[bp] = ffma2(x2, nn, a2[bp]);
            }
        }
    }
#pragma unroll
    for (int off = 16; off > 0; off >>= 1) {
#pragma unroll
        for (int bp = 0; bp < 8; bp++) {
            a0[bp].x += __shfl_xor_sync(0xffffffffu, a0[bp].x, off);
            a0[bp].y += __shfl_xor_sync(0xffffffffu, a0[bp].y, off);
            a1[bp].x += __shfl_xor_sync(0xffffffffu, a1[bp].x, off);
            a1[bp].y += __shfl_xor_sync(0xffffffffu, a1[bp].y, off);
            a2[bp].x += __shfl_xor_sync(0xffffffffu, a2[bp].x, off);
            a2[bp].y += __shfl_xor_sync(0xffffffffu, a2[bp].y, off);
        }
    }
    if (l == 0) {
        float* dst = ex + ((role * 2 + kh) * 4 + jrel) * 48;
#pragma unroll
        for (int bp = 0; bp < 8; bp++) {
            dst[2 * bp] = a0[bp].x;      dst[2 * bp + 1] = a0[bp].y;
            dst[16 + 2 * bp] = a1[bp].x; dst[16 + 2 * bp + 1] = a1[bp].y;
            dst[32 + 2 * bp] = a2[bp].x; dst[32 + 2 * bp + 1] = a2[bp].y;
        }
    }
    __syncthreads();
    if (tid < 64) {
        int b = tid & 15, jr = tid >> 4;
        int jj = bi * 4 + jr;
        const float* gi0 = ex + (0 * 4 + jr) * 48;
        const float* gi1 = ex + (1 * 4 + jr) * 48;
        const float* gh0 = ex + (2 * 4 + jr) * 48;
        const float* gh1 = ex + (3 * 4 + jr) * 48;
        float gir = gi0[b] + gi1[b], giz = gi0[16 + b] + gi1[16 + b], gin = gi0[32 + b] + gi1[32 + b];
        float ghr = gh0[b] + gh1[b], ghz = gh0[16 + b] + gh1[16 + b], ghn = gh0[32 + b] + gh1[32 + b];
        float r = hsig(gir + bih[jj] + ghr + bhh[jj]);
        float z = hsig(giz + bih[jj + 512] + ghz + bhh[jj + 512]);
        float n = htanh(gin + bih[jj + 1024] + r * (ghn + bhh[jj + 1024]));
        float hprev = hp[(b >> 1) * 1024 + 2 * jj + (b & 1)];
        hnew[b * HH + jj] = (1.f - z) * n + z * hprev;
    }
}

// tail: blocks 0..63 compute next-step hW1; block 64 out-proj + xin update
__device__ __forceinline__ void tail_phase(float* sm, int pn, int t,
                                           const float* __restrict__ attnW,
                                           const float* __restrict__ attnb,
                                           const float* __restrict__ outW,
                                           const float* __restrict__ outb,
                                           float* __restrict__ dout) {
    int bi = blockIdx.x;
    int tid = threadIdx.x;
    const float* h1 = g_h1[pn];

    if (bi < 64) {
        float* hp = sm;
        float* ex = sm + 16 * 512;
        for (int i = tid; i < 16 * 512; i += NTH) {
            int b = i >> 9, k = i & 511;
            hp[(b >> 1) * 1024 + 2 * k + (b & 1)] = lcg(h1 + b * HH + k);
        }
        __syncthreads();
        int w = tid >> 5, l = tid & 31;
        int jrel = w & 7, kh = w >> 3;
        int j = bi * 8 + jrel;
        const float2* hp2 = reinterpret_cast<const float2*>(hp);
        const float* wcol = attnW + (size_t)j * (2 * HH);
        float2 acc[8];
#pragma unroll
        for (int bp = 0; bp < 8; bp++) acc[bp] = make_float2(0.f, 0.f);
        int k0 = l + kh * 32;
#pragma unroll
        for (int ii = 0; ii < 8; ii++) {
            int k = k0 + ii * 64;
            float wv = wcol[k];
            float2 ww = make_float2(wv, wv);
#pragma unroll
            for (int bp = 0; bp < 8; bp++) acc[bp] = ffma2(hp2[bp * 512 + k], ww, acc[bp]);
        }
#pragma unroll
        for (int off = 16; off > 0; off >>= 1) {
#pragma unroll
            for (int bp = 0; bp < 8; bp++) {
                acc[bp].x += __shfl_xor_sync(0xffffffffu, acc[bp].x, off);
                acc[bp].y += __shfl_xor_sync(0xffffffffu, acc[bp].y, off);
            }
        }
        if (l == 0) {
            float* dst = ex + (kh * 8 + jrel) * 16;
#pragma unroll
            for (int bp = 0; bp < 8; bp++) { dst[2 * bp] = acc[bp].x; dst[2 * bp + 1] = acc[bp].y; }
        }
        __syncthreads();
        if (tid < 128) {
            int b = tid & 15, jr = tid >> 4;
            int jj = bi * 8 + jr;
            g_hW1[b * HH + jj] = ex[jr * 16 + b] + ex[(8 + jr) * 16 + b] + attnb[jj];
        }
    } else if (bi == 64 && t >= 0) {
        float* red = sm;
        int out = tid & 127, kc = tid >> 7;
        int b = out >> 3, f = out & 7;
        const float* wrow = outW + f * (2 * HH + FF);
        float acc = 0.f;
        if (kc < 2) {
            const float2* w2 = reinterpret_cast<const float2*>(wrow + kc * 256);
            const float* h2 = h1 + b * HH + kc * 256;
#pragma unroll 8
            for (int c = 0; c < 128; c++) {
                float2 wv = w2[c]; float2 hv = lcg2(h2 + 2 * c);
                acc += wv.x * hv.x + wv.y * hv.y;
            }
        } else {
            const float2* w2 = reinterpret_cast<const float2*>(wrow + 512 + (kc - 2) * 256);
            const float* g2 = g_weighted + b * HH + (kc - 2) * 256;
#pragma unroll 8
            for (int c = 0; c < 128; c++) {
                float2 wv = w2[c]; float2 gv = lcg2(g2 + 2 * c);
                acc += wv.x * gv.x + wv.y * gv.y;
            }
            if (kc == 3) {
#pragma unroll
                for (int c = 0; c < FF; c++) acc += wrow[2 * HH + c] * lcg(&g_xin[b * FF + c]);
                acc += outb[f];
            }
        }
        red[tid] = acc;
        __syncthreads();
        if (kc == 0) {
            float v = red[out] + red[out + 128] + red[out + 256] + red[out + 384];
            v = fmaxf(v, 0.f);
            dout[(b * TT + t) * FF + f] = v;
            g_xin[out] = v;   // next_in = out (TGT_IDX covers all F)
        }
    }
}

// ================== persistent kernel ==================
__global__ void __launch_bounds__(NTH, 1)
kPersist(const float* __restrict__ target, const float* __restrict__ hidden0,
         const float* __restrict__ enc, const float* __restrict__ attnW,
         const float* __restrict__ attnb, const float* __restrict__ v_w,
         const float* __restrict__ Wih0, const float* __restrict__ Whh0,
         const float* __restrict__ bih0, const float* __restrict__ bhh0,
         const float* __restrict__ Wih1, const float* __restrict__ Whh1,
         const float* __restrict__ bih1, const float* __restrict__ bhh1,
         const float* __restrict__ outW, const float* __restrict__ outb,
         float* __restrict__ dout)
{
    extern __shared__ float sm[];
    int tid = threadIdx.x, bi = blockIdx.x;

    for (int i = bi * NTH + tid; i < BB * HH; i += GRID * NTH) {
        g_h0[0][i] = hidden0[i];
        g_h1[0][i] = hidden0[BB * HH + i];
    }
    if (bi == 0 && tid < BB * FF) {
        int b = tid >> 3, f = tid & 7;
        g_xin[tid] = target[b * TT * FF + f];
    }
    gridbar();

    tail_phase(sm, 0, -1, attnW, attnb, outW, outb, dout);
    gridbar();

    for (int t = 0; t < TT; t++) {
        int p = t & 1, pn = 1 - p;
        scores_phase(v_w);
        gridbar();
        weighted_phase(sm, enc);
        gridbar();
        gru_phase<0>(sm, p, Wih0, Whh0, bih0, bhh0);
        gridbar();
        gru_phase<1>(sm, p, Wih1, Whh1, bih1, bhh1);
        gridbar();
        tail_phase(sm, pn, t, attnW, attnb, outW, outb, dout);
        gridbar();
    }
}

// ---------------- launch ----------------
extern "C" void kernel_launch(void* const* d_in, const int* in_sizes, int n_in,
                              void* d_out, int out_size) {
    (void)in_sizes; (void)n_in; (void)out_size;
    const float* target  = (const float*)d_in[0];
    const float* hidden0 = (const float*)d_in[1];
    const float* enc     = (const float*)d_in[2];
    const float* attnW   = (const float*)d_in[3];
    const float* attnb   = (const float*)d_in[4];
    const float* v_w     = (const float*)d_in[5];
    const float* Wih0    = (const float*)d_in[6];
    const float* Whh0    = (const float*)d_in[7];
    const float* bih0    = (const float*)d_in[8];
    const float* bhh0    = (const float*)d_in[9];
    const float* Wih1    = (const float*)d_in[10];
    const float* Whh1    = (const float*)d_in[11];
    const float* bih1    = (const float*)d_in[12];
    const float* bhh1    = (const float*)d_in[13];
    const float* outW    = (const float*)d_in[14];
    const float* outb    = (const float*)d_in[15];
    float* dout = (float*)d_out;

    const int smem = (16 * KX + 16 * 512 + 768) * 4;  // 69120 B
    static int cfg_done = 0;
    if (!cfg_done) {
        cudaFuncSetAttribute(kPersist, cudaFuncAttributeMaxDynamicSharedMemorySize, smem);
        cfg_done = 1;
    }

    kEncW2<<<dim3(8, 64), 256>>>(enc, attnW);
    kPersist<<<GRID, NTH, smem>>>(target, hidden0, enc, attnW, attnb, v_w,
                                  Wih0, Whh0, bih0, bhh0,
                                  Wih1, Whh1, bih1, bhh1,
                                  outW, outb, dout);
}